// round 15
// baseline (speedup 1.0000x reference)
#include <cuda_runtime.h>
#include <cuda_fp16.h>
#include <math.h>
#include <stdint.h>

#define NN 100000
#define NE 1600000
#define NG 32
#define DH 64
#define SCAN_NB 98
#define NB_NODE 3125      // NN / 32, exact
#define NB_WCONV 72       // ceil(3*6144 / 256)

typedef unsigned long long ull;

// ---------------- scratch ----------------
__device__ int      g_deg[NN];
__device__ float    g_dinv[NN];
__device__ int      g_rowptr[NN + 1];
__device__ int      g_col[NE];
__device__ uint16_t g_rank[NE];
__device__ ull      g_state[SCAN_NB];
__device__ __half   g_hh[NN * DH];            // fp16 unscaled features (z-term, GEMM X0, pool)
__device__ __half   g_x1h[NN * DH];           // fp16 X1 (GEMM operand)
__device__ __half   g_x2h[NN * DH];           // fp16 X2 (GEMM operand)
__device__ __align__(16) char g_ys8[NN * DH]; // int8 dinv-scaled features (gather operand)
__device__ float    g_ysc[NN];                // dequant scale for ys8
__device__ __align__(16) char g_x1s8[NN * DH];// int8 dinv-scaled X1 (gather operand)
__device__ float    g_x1sc[NN];               // dequant scale for x1s8
__device__ __half   g_wh[3 * 12288];          // fp16 W0|W1|W2
__device__ float    g_hg[NG * DH];

// ---------------- mma helpers ----------------
__device__ __forceinline__ uint32_t smem_u32(const void* p) {
    return (uint32_t)__cvta_generic_to_shared(p);
}
__device__ __forceinline__ void ldmx4(uint32_t* r, uint32_t addr) {
    asm volatile("ldmatrix.sync.aligned.m8n8.x4.shared.b16 {%0,%1,%2,%3}, [%4];"
                 : "=r"(r[0]), "=r"(r[1]), "=r"(r[2]), "=r"(r[3]) : "r"(addr));
}
__device__ __forceinline__ void ldmx4t(uint32_t* r, uint32_t addr) {
    asm volatile("ldmatrix.sync.aligned.m8n8.x4.trans.shared.b16 {%0,%1,%2,%3}, [%4];"
                 : "=r"(r[0]), "=r"(r[1]), "=r"(r[2]), "=r"(r[3]) : "r"(addr));
}
__device__ __forceinline__ void mma16816(float* c, const uint32_t* a, const uint32_t* b) {
    asm volatile("mma.sync.aligned.m16n8k16.row.col.f32.f16.f16.f32 "
                 "{%0,%1,%2,%3}, {%4,%5,%6,%7}, {%8,%9}, {%0,%1,%2,%3};"
                 : "+f"(c[0]), "+f"(c[1]), "+f"(c[2]), "+f"(c[3])
                 : "r"(a[0]), "r"(a[1]), "r"(a[2]), "r"(a[3]), "r"(b[0]), "r"(b[1]));
}

// ---------------- CSR build ----------------
__global__ void k_hist(const int* __restrict__ dst) {
    int t = blockIdx.x * blockDim.x + threadIdx.x;
    if (t * 8 >= NE) return;
    int4 d0 = ((const int4*)dst)[t * 2];
    int4 d1 = ((const int4*)dst)[t * 2 + 1];
    int r0 = atomicAdd(&g_deg[d0.x], 1);
    int r1 = atomicAdd(&g_deg[d0.y], 1);
    int r2 = atomicAdd(&g_deg[d0.z], 1);
    int r3 = atomicAdd(&g_deg[d0.w], 1);
    int r4 = atomicAdd(&g_deg[d1.x], 1);
    int r5 = atomicAdd(&g_deg[d1.y], 1);
    int r6 = atomicAdd(&g_deg[d1.z], 1);
    int r7 = atomicAdd(&g_deg[d1.w], 1);
    ushort4 a, b;
    a.x = (uint16_t)r0; a.y = (uint16_t)r1; a.z = (uint16_t)r2; a.w = (uint16_t)r3;
    b.x = (uint16_t)r4; b.y = (uint16_t)r5; b.z = (uint16_t)r6; b.w = (uint16_t)r7;
    ((ushort4*)g_rank)[t * 2] = a;
    ((ushort4*)g_rank)[t * 2 + 1] = b;
}

__global__ void k_scan() {
    int tid = threadIdx.x, bid = blockIdx.x;
    int i = bid * 1024 + tid;
    int deg = (i < NN) ? g_deg[i] : 0;
    int lane = tid & 31, wid = tid >> 5;

    int incl = deg;
    #pragma unroll
    for (int o = 1; o < 32; o <<= 1) {
        int t = __shfl_up_sync(0xFFFFFFFFu, incl, o);
        if (lane >= o) incl += t;
    }
    __shared__ int wsum[32];
    if (lane == 31) wsum[wid] = incl;
    __syncthreads();
    if (wid == 0) {
        int v = wsum[lane];
        int s = v;
        #pragma unroll
        for (int o = 1; o < 32; o <<= 1) {
            int t = __shfl_up_sync(0xFFFFFFFFu, s, o);
            if (lane >= o) s += t;
        }
        wsum[lane] = s - v;
    }
    __syncthreads();
    int excl = incl - deg + wsum[wid];

    __shared__ int btotal;
    if (tid == 1023) btotal = excl + deg;
    __syncthreads();
    if (tid == 0) {
        __threadfence();
        atomicExch(&g_state[bid], ((ull)btotal) | (1ull << 40));
    }
    __shared__ int aggs[SCAN_NB];
    if (tid < SCAN_NB) {
        ull v;
        do { v = atomicAdd(&g_state[tid], 0ull); } while (!(v >> 40));
        aggs[tid] = (int)(v & 0xFFFFFFFFull);
    }
    __syncthreads();
    __shared__ int sbase, stotal;
    if (tid == 0) {
        int b = 0, tot = 0;
        #pragma unroll 2
        for (int j = 0; j < SCAN_NB; j++) {
            if (j < bid) b += aggs[j];
            tot += aggs[j];
        }
        sbase = b; stotal = tot;
    }
    __syncthreads();
    if (i < NN) {
        g_rowptr[i] = sbase + excl;
        g_dinv[i] = rsqrtf(fmaxf((float)deg, 1.0f));
    }
    if (bid == SCAN_NB - 1 && tid == 0) g_rowptr[NN] = stotal;
}

__global__ void k_fill(const int* __restrict__ src, const int* __restrict__ dst) {
    int t = blockIdx.x * blockDim.x + threadIdx.x;
    if (t * 8 >= NE) return;
    int4 d0 = ((const int4*)dst)[t * 2];
    int4 d1 = ((const int4*)dst)[t * 2 + 1];
    int4 s0 = ((const int4*)src)[t * 2];
    int4 s1 = ((const int4*)src)[t * 2 + 1];
    ushort4 a = ((const ushort4*)g_rank)[t * 2];
    ushort4 b = ((const ushort4*)g_rank)[t * 2 + 1];
    g_col[g_rowptr[d0.x] + a.x] = s0.x;
    g_col[g_rowptr[d0.y] + a.y] = s0.y;
    g_col[g_rowptr[d0.z] + a.z] = s0.z;
    g_col[g_rowptr[d0.w] + a.w] = s0.w;
    g_col[g_rowptr[d1.x] + b.x] = s1.x;
    g_col[g_rowptr[d1.y] + b.y] = s1.y;
    g_col[g_rowptr[d1.z] + b.z] = s1.z;
    g_col[g_rowptr[d1.w] + b.w] = s1.w;
}

// ---------------- int8 quant/dequant helpers ----------------
__device__ __forceinline__ int bext(uint32_t p, int j) {
    int r;
    asm("dp4a.s32.s32 %0, %1, %2, %3;" : "=r"(r) : "r"(p), "r"(1 << (8 * j)), "r"(0));
    return r;
}
__device__ __forceinline__ void accq(float* a, uint2 v, float sc) {
    a[0] += sc * (float)bext(v.x, 0);
    a[1] += sc * (float)bext(v.x, 1);
    a[2] += sc * (float)bext(v.x, 2);
    a[3] += sc * (float)bext(v.x, 3);
    a[4] += sc * (float)bext(v.y, 0);
    a[5] += sc * (float)bext(v.y, 1);
    a[6] += sc * (float)bext(v.y, 2);
    a[7] += sc * (float)bext(v.y, 3);
}
__device__ __forceinline__ uint2 pack8(const float* q, float sq) {
    int q0 = __float2int_rn(q[0] * sq), q1 = __float2int_rn(q[1] * sq);
    int q2 = __float2int_rn(q[2] * sq), q3 = __float2int_rn(q[3] * sq);
    int q4 = __float2int_rn(q[4] * sq), q5 = __float2int_rn(q[5] * sq);
    int q6 = __float2int_rn(q[6] * sq), q7 = __float2int_rn(q[7] * sq);
    uint2 pk;
    pk.x = (q0 & 0xFF) | ((q1 & 0xFF) << 8) | ((q2 & 0xFF) << 16) | ((q3 & 0xFF) << 24);
    pk.y = (q4 & 0xFF) | ((q5 & 0xFF) << 8) | ((q6 & 0xFF) << 16) | ((q7 & 0xFF) << 24);
    return pk;
}

// int8 gather: per edge one 64B row + one 4B scale (broadcast)
__device__ __forceinline__ void gatherq(const char* __restrict__ q8,
                                        const float* __restrict__ qsc,
                                        int s, int e, int lane, float* a) {
    const uint2* yp = (const uint2*)q8;
    int i = s;
    for (; i + 4 <= e; i += 4) {
        int c0 = g_col[i], c1 = g_col[i + 1], c2 = g_col[i + 2], c3 = g_col[i + 3];
        uint2 v0 = yp[c0 * 8 + lane];
        uint2 v1 = yp[c1 * 8 + lane];
        uint2 v2 = yp[c2 * 8 + lane];
        uint2 v3 = yp[c3 * 8 + lane];
        float sc0 = qsc[c0], sc1 = qsc[c1], sc2 = qsc[c2], sc3 = qsc[c3];
        accq(a, v0, sc0); accq(a, v1, sc1); accq(a, v2, sc2); accq(a, v3, sc3);
    }
    for (; i < e; i++) {
        int c = g_col[i];
        accq(a, yp[c * 8 + lane], qsc[c]);
    }
}

// ---------------- k_pre: layer-0 prescale+quant, W conversion folded ----------
// Node blocks [0, NB_NODE): 8 lanes/node. W blocks [NB_NODE, NB_NODE+NB_WCONV).
__global__ void k_pre(const float* __restrict__ x, const float* __restrict__ W0,
                      const float* __restrict__ W1, const float* __restrict__ W2) {
    int bid = blockIdx.x;
    if (bid >= NB_NODE) {
        int i = (bid - NB_NODE) * 256 + threadIdx.x;   // half2 index
        if (i < 3 * 6144) {
            int l = i / 6144, r = i % 6144;
            const float* W = (l == 0) ? W0 : (l == 1) ? W1 : W2;
            float2 v = ((const float2*)W)[r];
            ((__half2*)g_wh)[i] = __floats2half2_rn(v.x, v.y);
        }
        return;
    }
    int node = bid * 32 + (threadIdx.x >> 3);
    int lane = threadIdx.x & 7;
    float di = g_dinv[node];
    float4 va = ((const float4*)x)[node * 16 + lane * 2];
    float4 vb = ((const float4*)x)[node * 16 + lane * 2 + 1];
    float v[8] = {va.x, va.y, va.z, va.w, vb.x, vb.y, vb.z, vb.w};
    // hh fp16
    uint4 wh;
    *(__half2*)&wh.x = __floats2half2_rn(v[0], v[1]);
    *(__half2*)&wh.y = __floats2half2_rn(v[2], v[3]);
    *(__half2*)&wh.z = __floats2half2_rn(v[4], v[5]);
    *(__half2*)&wh.w = __floats2half2_rn(v[6], v[7]);
    ((uint4*)g_hh)[node * 8 + lane] = wh;
    // hs int8 quant
    float q[8], m = 0.f;
    #pragma unroll
    for (int j = 0; j < 8; j++) { q[j] = v[j] * di; m = fmaxf(m, fabsf(q[j])); }
    m = fmaxf(m, __shfl_xor_sync(0xFFFFFFFFu, m, 1));
    m = fmaxf(m, __shfl_xor_sync(0xFFFFFFFFu, m, 2));
    m = fmaxf(m, __shfl_xor_sync(0xFFFFFFFFu, m, 4));
    float sq = (m > 0.f) ? 127.f / m : 0.f;
    ((uint2*)g_ys8)[node * 8 + lane] = pack8(q, sq);
    if (lane == 0) g_ysc[node] = m * (1.f / 127.f);
}

// ---------------- SpMM1: int8 gather -> X1h fp16 + x1s8 int8 ------------------
__global__ void k_spmm1() {
    int node = blockIdx.x * 32 + (threadIdx.x >> 3);
    int lane = threadIdx.x & 7;
    int s = g_rowptr[node], e = g_rowptr[node + 1];
    float a[8] = {0.f, 0.f, 0.f, 0.f, 0.f, 0.f, 0.f, 0.f};
    gatherq(g_ys8, g_ysc, s, e, lane, a);
    float di = g_dinv[node];
    float s1 = -di, s2 = -di * di;
    uint4 w1;
    *(__half2*)&w1.x = __floats2half2_rn(s1 * a[0], s1 * a[1]);
    *(__half2*)&w1.y = __floats2half2_rn(s1 * a[2], s1 * a[3]);
    *(__half2*)&w1.z = __floats2half2_rn(s1 * a[4], s1 * a[5]);
    *(__half2*)&w1.w = __floats2half2_rn(s1 * a[6], s1 * a[7]);
    ((uint4*)g_x1h)[node * 8 + lane] = w1;
    float q[8], m = 0.f;
    #pragma unroll
    for (int j = 0; j < 8; j++) { q[j] = s2 * a[j]; m = fmaxf(m, fabsf(q[j])); }
    m = fmaxf(m, __shfl_xor_sync(0xFFFFFFFFu, m, 1));
    m = fmaxf(m, __shfl_xor_sync(0xFFFFFFFFu, m, 2));
    m = fmaxf(m, __shfl_xor_sync(0xFFFFFFFFu, m, 4));
    float sq = (m > 0.f) ? 127.f / m : 0.f;
    ((uint2*)g_x1s8)[node * 8 + lane] = pack8(q, sq);
    if (lane == 0) g_x1sc[node] = m * (1.f / 127.f);
}

// ---------------- SpMM2: int8 gather -> X2h = -2*dinv*(A x1s) - hh ------------
__global__ void k_spmm2() {
    int node = blockIdx.x * 32 + (threadIdx.x >> 3);
    int lane = threadIdx.x & 7;
    int s = g_rowptr[node], e = g_rowptr[node + 1];
    float a[8] = {0.f, 0.f, 0.f, 0.f, 0.f, 0.f, 0.f, 0.f};
    gatherq(g_x1s8, g_x1sc, s, e, lane, a);
    float m = -2.f * g_dinv[node];
    uint4 zv = ((const uint4*)g_hh)[node * 8 + lane];
    float2 z0 = __half22float2(*(const __half2*)&zv.x);
    float2 z1 = __half22float2(*(const __half2*)&zv.y);
    float2 z2 = __half22float2(*(const __half2*)&zv.z);
    float2 z3 = __half22float2(*(const __half2*)&zv.w);
    uint4 w;
    *(__half2*)&w.x = __floats2half2_rn(m * a[0] - z0.x, m * a[1] - z0.y);
    *(__half2*)&w.y = __floats2half2_rn(m * a[2] - z1.x, m * a[3] - z1.y);
    *(__half2*)&w.z = __floats2half2_rn(m * a[4] - z2.x, m * a[5] - z2.y);
    *(__half2*)&w.w = __floats2half2_rn(m * a[6] - z3.x, m * a[7] - z3.y);
    ((uint4*)g_x2h)[node * 8 + lane] = w;
}

// ---------------- GEMM (HMMA): out = [X0|X1|X2] @ Wh + b ----------------------
// Epilogue: write hh fp16; if outQ8 != null also write int8 quantized hs_next.
__global__ void k_gemm(const __half* __restrict__ x0, const __half* __restrict__ x1,
                       const __half* __restrict__ x2,
                       const __half* __restrict__ Wh, const float* __restrict__ bias,
                       __half* __restrict__ outH, char* __restrict__ outQ8,
                       float* __restrict__ outQsc, int relu) {
    __shared__ __align__(16) __half Xs[128 * 72];
    __shared__ __align__(16) __half Ws[64 * 72];
    int tid = threadIdx.x;
    int warp = tid >> 5, lane = tid & 31;
    int n0 = blockIdx.x * 128;

    float acc[2][8][4];
    #pragma unroll
    for (int tm = 0; tm < 2; tm++)
        #pragma unroll
        for (int nt = 0; nt < 8; nt++)
            #pragma unroll
            for (int q = 0; q < 4; q++) acc[tm][nt][q] = 0.f;

    const __half* xp[3] = {x0, x1, x2};
    for (int p = 0; p < 3; p++) {
        const __half* xc = xp[p];
        #pragma unroll
        for (int i = 0; i < 8; i++) {
            int li = i * 128 + tid;
            int row = li >> 3, c = li & 7;
            int gn = n0 + row;
            uint4 v = (gn < NN) ? ((const uint4*)xc)[gn * 8 + c]
                                : make_uint4(0u, 0u, 0u, 0u);
            *(uint4*)&Xs[row * 72 + c * 8] = v;
        }
        #pragma unroll
        for (int i = 0; i < 8; i++) {
            int li = i * 128 + tid;
            int row = li >> 4, c = li & 15;
            uint2 pk = ((const uint2*)(Wh + p * 4096))[li];
            *(uint2*)&Ws[row * 72 + c * 4] = pk;
        }
        __syncthreads();
        #pragma unroll
        for (int ks = 0; ks < 4; ks++) {
            int kb = ks * 16;
            uint32_t A[2][4];
            #pragma unroll
            for (int tm = 0; tm < 2; tm++) {
                int r = warp * 32 + tm * 16 + (lane & 15);
                ldmx4(A[tm], smem_u32(&Xs[r * 72 + kb + (lane >> 4) * 8]));
            }
            uint32_t B[8][2];
            #pragma unroll
            for (int g = 0; g < 4; g++) {
                uint32_t t[4];
                int krow = kb + (lane & 15);
                ldmx4t(t, smem_u32(&Ws[krow * 72 + g * 16 + (lane >> 4) * 8]));
                B[g * 2 + 0][0] = t[0]; B[g * 2 + 0][1] = t[1];
                B[g * 2 + 1][0] = t[2]; B[g * 2 + 1][1] = t[3];
            }
            #pragma unroll
            for (int tm = 0; tm < 2; tm++)
                #pragma unroll
                for (int nt = 0; nt < 8; nt++)
                    mma16816(acc[tm][nt], A[tm], B[nt]);
        }
        __syncthreads();
    }

    int col = 2 * (lane & 3);
    #pragma unroll
    for (int tm = 0; tm < 2; tm++) {
        #pragma unroll
        for (int hf = 0; hf < 2; hf++) {
            int node = n0 + warp * 32 + tm * 16 + (lane >> 2) + hf * 8;
            bool valid = (node < NN);
            float di = valid ? g_dinv[node] : 0.f;
            float vv0[8], vv1[8];
            float m = 0.f;
            #pragma unroll
            for (int nt = 0; nt < 8; nt++) {
                int f = nt * 8 + col;
                float2 bv = *(const float2*)&bias[f];
                float v0 = acc[tm][nt][hf * 2 + 0] + bv.x;
                float v1 = acc[tm][nt][hf * 2 + 1] + bv.y;
                if (relu) { v0 = fmaxf(v0, 0.f); v1 = fmaxf(v1, 0.f); }
                if (valid) *(__half2*)&outH[node * DH + f] = __floats2half2_rn(v0, v1);
                vv0[nt] = v0 * di; vv1[nt] = v1 * di;
                m = fmaxf(m, fmaxf(fabsf(vv0[nt]), fabsf(vv1[nt])));
            }
            if (outQ8) {
                // quad (lanes sharing this node) row-max; shfl unconditional
                m = fmaxf(m, __shfl_xor_sync(0xFFFFFFFFu, m, 1));
                m = fmaxf(m, __shfl_xor_sync(0xFFFFFFFFu, m, 2));
                float sq = (m > 0.f) ? 127.f / m : 0.f;
                if (valid) {
                    #pragma unroll
                    for (int nt = 0; nt < 8; nt++) {
                        int f = nt * 8 + col;
                        int q0 = __float2int_rn(vv0[nt] * sq);
                        int q1 = __float2int_rn(vv1[nt] * sq);
                        uint16_t pk = (uint16_t)((q0 & 0xFF) | ((q1 & 0xFF) << 8));
                        *(uint16_t*)&outQ8[node * DH + f] = pk;
                    }
                    if ((lane & 3) == 0) outQsc[node] = m * (1.f / 127.f);
                }
            }
        }
    }
}

// ---------------- readout ----------------
__device__ __forceinline__ void acc8h(float* a, uint4 v) {
    float2 f0 = __half22float2(*(const __half2*)&v.x);
    float2 f1 = __half22float2(*(const __half2*)&v.y);
    float2 f2 = __half22float2(*(const __half2*)&v.z);
    float2 f3 = __half22float2(*(const __half2*)&v.w);
    a[0] += f0.x; a[1] += f0.y; a[2] += f1.x; a[3] += f1.y;
    a[4] += f2.x; a[5] += f2.y; a[6] += f3.x; a[7] += f3.y;
}

__global__ void k_pool(const __half* __restrict__ h, const int* __restrict__ gids) {
    int g = blockIdx.x;
    __shared__ int bnd[2];
    if (threadIdx.x < 2) {
        int target = g + threadIdx.x;
        int lo = 0, hi = NN;
        while (lo < hi) {
            int mid = (lo + hi) >> 1;
            if (gids[mid] < target) lo = mid + 1; else hi = mid;
        }
        bnd[threadIdx.x] = lo;
    }
    __syncthreads();
    int s = bnd[0], e = bnd[1];
    int f4 = threadIdx.x & 7;
    int way = threadIdx.x >> 3;
    float a[8] = {0.f, 0.f, 0.f, 0.f, 0.f, 0.f, 0.f, 0.f};
    for (int n = s + way; n < e; n += 32) {
        uint4 v = ((const uint4*)(h + n * DH))[f4];
        acc8h(a, v);
    }
    __shared__ float sm[32][64];
    #pragma unroll
    for (int j = 0; j < 8; j++) sm[way][f4 * 8 + j] = a[j];
    __syncthreads();
    if (threadIdx.x < 64) {
        float v = 0.f;
        #pragma unroll 8
        for (int w = 0; w < 32; w++) v += sm[w][threadIdx.x];
        float cnt = (float)(e - s);
        g_hg[g * DH + threadIdx.x] = v / fmaxf(cnt, 1.f);
    }
}

__global__ void k_mlp(const float* __restrict__ M0w, const float* __restrict__ M0b,
                      const float* __restrict__ M1w, const float* __restrict__ M1b,
                      const float* __restrict__ M2w, const float* __restrict__ M2b,
                      float* __restrict__ out) {
    __shared__ float h0[NG * 64];
    __shared__ float h1[NG * 32];
    __shared__ float h2[NG * 16];
    int tid = threadIdx.x;
    for (int i = tid; i < NG * 64; i += blockDim.x) h0[i] = g_hg[i];
    __syncthreads();
    if (tid < NG * 32) {
        int g = tid >> 5, f = tid & 31;
        float a = M0b[f];
        #pragma unroll
        for (int k = 0; k < 64; k++) a += h0[g * 64 + k] * M0w[k * 32 + f];
        h1[tid] = fmaxf(a, 0.f);
    }
    __syncthreads();
    if (tid < NG * 16) {
        int g = tid >> 4, f = tid & 15;
        float a = M1b[f];
        #pragma unroll
        for (int k = 0; k < 32; k++) a += h1[g * 32 + k] * M1w[k * 16 + f];
        h2[tid] = fmaxf(a, 0.f);
    }
    __syncthreads();
    if (tid < NG * 3) {
        int g = tid / 3, f = tid % 3;
        float a = M2b[f];
        #pragma unroll
        for (int k = 0; k < 16; k++) a += h2[g * 16 + k] * M2w[k * 3 + f];
        out[tid] = a;
    }
}

// ---------------- launch ----------------
extern "C" void kernel_launch(void* const* d_in, const int* in_sizes, int n_in,
                              void* d_out, int out_size) {
    const float* h    = (const float*)d_in[0];
    const int*   src  = (const int*)d_in[1];
    const int*   dst  = (const int*)d_in[2];
    const int*   gids = (const int*)d_in[3];
    const float* W0   = (const float*)d_in[4];
    const float* b0   = (const float*)d_in[5];
    const float* W1   = (const float*)d_in[6];
    const float* b1   = (const float*)d_in[7];
    const float* W2   = (const float*)d_in[8];
    const float* b2   = (const float*)d_in[9];
    const float* M0w  = (const float*)d_in[10];
    const float* M0b  = (const float*)d_in[11];
    const float* M1w  = (const float*)d_in[12];
    const float* M1b  = (const float*)d_in[13];
    const float* M2w  = (const float*)d_in[14];
    const float* M2b  = (const float*)d_in[15];
    float* out = (float*)d_out;

    __half *pHh, *pX1h, *pX2h, *pWh;
    char *pYs8;
    float *pYsc;
    int *pDeg;
    ull *pState;
    cudaGetSymbolAddress((void**)&pHh, g_hh);
    cudaGetSymbolAddress((void**)&pX1h, g_x1h);
    cudaGetSymbolAddress((void**)&pX2h, g_x2h);
    cudaGetSymbolAddress((void**)&pWh, g_wh);
    cudaGetSymbolAddress((void**)&pYs8, g_ys8);
    cudaGetSymbolAddress((void**)&pYsc, g_ysc);
    cudaGetSymbolAddress((void**)&pDeg, g_deg);
    cudaGetSymbolAddress((void**)&pState, g_state);

    const int nb_e8 = (NE / 8 + 255) / 256;
    const int nb_gemm = (NN + 127) / 128;

    // CSR build
    cudaMemsetAsync(pDeg, 0, NN * sizeof(int));
    cudaMemsetAsync(pState, 0, SCAN_NB * sizeof(ull));
    k_hist<<<nb_e8, 256>>>(dst);
    k_scan<<<SCAN_NB, 1024>>>();
    k_fill<<<nb_e8, 256>>>(src, dst);

    // layer 0 (k_pre also converts W)
    k_pre<<<NB_NODE + NB_WCONV, 256>>>(h, W0, W1, W2);
    k_spmm1<<<NB_NODE, 256>>>();
    k_spmm2<<<NB_NODE, 256>>>();
    k_gemm<<<nb_gemm, 128>>>(pHh, pX1h, pX2h, pWh, b0, pHh, pYs8, pYsc, 1);

    // layer 1
    k_spmm1<<<NB_NODE, 256>>>();
    k_spmm2<<<NB_NODE, 256>>>();
    k_gemm<<<nb_gemm, 128>>>(pHh, pX1h, pX2h, pWh + 12288, b1, pHh, pYs8, pYsc, 1);

    // layer 2 (no relu, fp16 out only)
    k_spmm1<<<NB_NODE, 256>>>();
    k_spmm2<<<NB_NODE, 256>>>();
    k_gemm<<<nb_gemm, 128>>>(pHh, pX1h, pX2h, pWh + 24576, b2, pHh, nullptr, nullptr, 0);

    // readout
    k_pool<<<NG, 256>>>(pHh, gids);
    k_mlp<<<1, 1024>>>(M0w, M0b, M1w, M1b, M2w, M2b, out);
}

// round 16
// speedup vs baseline: 1.0799x; 1.0799x over previous
#include <cuda_runtime.h>
#include <cuda_fp16.h>
#include <math.h>
#include <stdint.h>

#define NN 100000
#define NE 1600000
#define NG 32
#define DH 64
#define SCAN_NB 98

typedef unsigned long long ull;

// ---------------- scratch ----------------
__device__ int      g_deg[NN];
__device__ float    g_dinv[NN];
__device__ int      g_rowptr[NN + 1];
__device__ int      g_col[NE];
__device__ uint16_t g_rank[NE];
__device__ ull      g_state[SCAN_NB];
__device__ __half   g_hh[NN * DH];
__device__ __half   g_hs[NN * DH];
__device__ __half   g_x1h[NN * DH];
__device__ __half   g_x1s[NN * DH];
__device__ __half   g_x2h[NN * DH];
__device__ float    g_hg[NG * DH];

// ---------------- mma helpers ----------------
__device__ __forceinline__ uint32_t smem_u32(const void* p) {
    return (uint32_t)__cvta_generic_to_shared(p);
}
__device__ __forceinline__ void ldmx4(uint32_t* r, uint32_t addr) {
    asm volatile("ldmatrix.sync.aligned.m8n8.x4.shared.b16 {%0,%1,%2,%3}, [%4];"
                 : "=r"(r[0]), "=r"(r[1]), "=r"(r[2]), "=r"(r[3]) : "r"(addr));
}
__device__ __forceinline__ void ldmx4t(uint32_t* r, uint32_t addr) {
    asm volatile("ldmatrix.sync.aligned.m8n8.x4.trans.shared.b16 {%0,%1,%2,%3}, [%4];"
                 : "=r"(r[0]), "=r"(r[1]), "=r"(r[2]), "=r"(r[3]) : "r"(addr));
}
__device__ __forceinline__ void mma16816(float* c, const uint32_t* a, const uint32_t* b) {
    asm volatile("mma.sync.aligned.m16n8k16.row.col.f32.f16.f16.f32 "
                 "{%0,%1,%2,%3}, {%4,%5,%6,%7}, {%8,%9}, {%0,%1,%2,%3};"
                 : "+f"(c[0]), "+f"(c[1]), "+f"(c[2]), "+f"(c[3])
                 : "r"(a[0]), "r"(a[1]), "r"(a[2]), "r"(a[3]), "r"(b[0]), "r"(b[1]));
}

// ---------------- CSR build ----------------
__global__ void k_hist(const int* __restrict__ dst) {
    int t = blockIdx.x * blockDim.x + threadIdx.x;
    if (t * 8 >= NE) return;
    int4 d0 = ((const int4*)dst)[t * 2];
    int4 d1 = ((const int4*)dst)[t * 2 + 1];
    int r0 = atomicAdd(&g_deg[d0.x], 1);
    int r1 = atomicAdd(&g_deg[d0.y], 1);
    int r2 = atomicAdd(&g_deg[d0.z], 1);
    int r3 = atomicAdd(&g_deg[d0.w], 1);
    int r4 = atomicAdd(&g_deg[d1.x], 1);
    int r5 = atomicAdd(&g_deg[d1.y], 1);
    int r6 = atomicAdd(&g_deg[d1.z], 1);
    int r7 = atomicAdd(&g_deg[d1.w], 1);
    ushort4 a, b;
    a.x = (uint16_t)r0; a.y = (uint16_t)r1; a.z = (uint16_t)r2; a.w = (uint16_t)r3;
    b.x = (uint16_t)r4; b.y = (uint16_t)r5; b.z = (uint16_t)r6; b.w = (uint16_t)r7;
    ((ushort4*)g_rank)[t * 2] = a;
    ((ushort4*)g_rank)[t * 2 + 1] = b;
}

__global__ void k_scan() {
    int tid = threadIdx.x, bid = blockIdx.x;
    int i = bid * 1024 + tid;
    int deg = (i < NN) ? g_deg[i] : 0;
    int lane = tid & 31, wid = tid >> 5;

    int incl = deg;
    #pragma unroll
    for (int o = 1; o < 32; o <<= 1) {
        int t = __shfl_up_sync(0xFFFFFFFFu, incl, o);
        if (lane >= o) incl += t;
    }
    __shared__ int wsum[32];
    if (lane == 31) wsum[wid] = incl;
    __syncthreads();
    if (wid == 0) {
        int v = wsum[lane];
        int s = v;
        #pragma unroll
        for (int o = 1; o < 32; o <<= 1) {
            int t = __shfl_up_sync(0xFFFFFFFFu, s, o);
            if (lane >= o) s += t;
        }
        wsum[lane] = s - v;
    }
    __syncthreads();
    int excl = incl - deg + wsum[wid];

    __shared__ int btotal;
    if (tid == 1023) btotal = excl + deg;
    __syncthreads();
    if (tid == 0) {
        __threadfence();
        atomicExch(&g_state[bid], ((ull)btotal) | (1ull << 40));
    }
    __shared__ int aggs[SCAN_NB];
    if (tid < SCAN_NB) {
        ull v;
        do { v = atomicAdd(&g_state[tid], 0ull); } while (!(v >> 40));
        aggs[tid] = (int)(v & 0xFFFFFFFFull);
    }
    __syncthreads();
    __shared__ int sbase, stotal;
    if (tid == 0) {
        int b = 0, tot = 0;
        #pragma unroll 2
        for (int j = 0; j < SCAN_NB; j++) {
            if (j < bid) b += aggs[j];
            tot += aggs[j];
        }
        sbase = b; stotal = tot;
    }
    __syncthreads();
    if (i < NN) {
        g_rowptr[i] = sbase + excl;
        g_dinv[i] = rsqrtf(fmaxf((float)deg, 1.0f));
    }
    if (bid == SCAN_NB - 1 && tid == 0) g_rowptr[NN] = stotal;
}

__global__ void k_fill(const int* __restrict__ src, const int* __restrict__ dst) {
    int t = blockIdx.x * blockDim.x + threadIdx.x;
    if (t * 8 >= NE) return;
    int4 d0 = ((const int4*)dst)[t * 2];
    int4 d1 = ((const int4*)dst)[t * 2 + 1];
    int4 s0 = ((const int4*)src)[t * 2];
    int4 s1 = ((const int4*)src)[t * 2 + 1];
    ushort4 a = ((const ushort4*)g_rank)[t * 2];
    ushort4 b = ((const ushort4*)g_rank)[t * 2 + 1];
    g_col[g_rowptr[d0.x] + a.x] = s0.x;
    g_col[g_rowptr[d0.y] + a.y] = s0.y;
    g_col[g_rowptr[d0.z] + a.z] = s0.z;
    g_col[g_rowptr[d0.w] + a.w] = s0.w;
    g_col[g_rowptr[d1.x] + b.x] = s1.x;
    g_col[g_rowptr[d1.y] + b.y] = s1.y;
    g_col[g_rowptr[d1.z] + b.z] = s1.z;
    g_col[g_rowptr[d1.w] + b.w] = s1.w;
}

// ---------------- prescale (layer 0): hs = half(dinv.*x), hh = half(x) --------
__global__ void k_pre(const float* __restrict__ x) {
    int i = blockIdx.x * blockDim.x + threadIdx.x;
    if (i < NN * 32) {
        float2 v = ((const float2*)x)[i];
        float di = g_dinv[i >> 5];
        ((__half2*)g_hs)[i] = __floats2half2_rn(v.x * di, v.y * di);
        ((__half2*)g_hh)[i] = __floats2half2_rn(v.x, v.y);
    }
}

// ---------------- gather helpers ----------------
__device__ __forceinline__ void acc8(float* a, uint4 v) {
    float2 f0 = __half22float2(*(const __half2*)&v.x);
    float2 f1 = __half22float2(*(const __half2*)&v.y);
    float2 f2 = __half22float2(*(const __half2*)&v.z);
    float2 f3 = __half22float2(*(const __half2*)&v.w);
    a[0] += f0.x; a[1] += f0.y; a[2] += f1.x; a[3] += f1.y;
    a[4] += f2.x; a[5] += f2.y; a[6] += f3.x; a[7] += f3.y;
}

// x8-batched gather: 8 independent gathers per iteration (MLP=8), plain batch
// (no register rotation), x4 + x1 remainder.
__device__ __forceinline__ void gather_rows(const uint4* __restrict__ yp,
                                            int s, int e, int lane, float* a) {
    int i = s;
    for (; i + 8 <= e; i += 8) {
        int c0 = g_col[i],     c1 = g_col[i + 1], c2 = g_col[i + 2], c3 = g_col[i + 3];
        int c4 = g_col[i + 4], c5 = g_col[i + 5], c6 = g_col[i + 6], c7 = g_col[i + 7];
        uint4 v0 = yp[c0 * 8 + lane];
        uint4 v1 = yp[c1 * 8 + lane];
        uint4 v2 = yp[c2 * 8 + lane];
        uint4 v3 = yp[c3 * 8 + lane];
        uint4 v4 = yp[c4 * 8 + lane];
        uint4 v5 = yp[c5 * 8 + lane];
        uint4 v6 = yp[c6 * 8 + lane];
        uint4 v7 = yp[c7 * 8 + lane];
        acc8(a, v0); acc8(a, v1); acc8(a, v2); acc8(a, v3);
        acc8(a, v4); acc8(a, v5); acc8(a, v6); acc8(a, v7);
    }
    for (; i + 4 <= e; i += 4) {
        int c0 = g_col[i], c1 = g_col[i + 1], c2 = g_col[i + 2], c3 = g_col[i + 3];
        uint4 v0 = yp[c0 * 8 + lane];
        uint4 v1 = yp[c1 * 8 + lane];
        uint4 v2 = yp[c2 * 8 + lane];
        uint4 v3 = yp[c3 * 8 + lane];
        acc8(a, v0); acc8(a, v1); acc8(a, v2); acc8(a, v3);
    }
    for (; i < e; i++) {
        uint4 v = yp[g_col[i] * 8 + lane];
        acc8(a, v);
    }
}

// ---------------- SpMM1: X1h = half(-dinv.*(A hs)); X1s = half(dinv.*X1) ------
__global__ void k_spmm1(const __half* __restrict__ ys, __half* __restrict__ X1h,
                        __half* __restrict__ X1s) {
    int node = blockIdx.x * (blockDim.x >> 3) + (threadIdx.x >> 3);
    int lane = threadIdx.x & 7;
    if (node >= NN) return;
    int s = g_rowptr[node], e = g_rowptr[node + 1];
    float a[8] = {0.f, 0.f, 0.f, 0.f, 0.f, 0.f, 0.f, 0.f};
    gather_rows((const uint4*)ys, s, e, lane, a);
    float di = g_dinv[node];
    float s1 = -di;
    float s2 = -di * di;
    uint4 w1, w2;
    *(__half2*)&w1.x = __floats2half2_rn(s1 * a[0], s1 * a[1]);
    *(__half2*)&w1.y = __floats2half2_rn(s1 * a[2], s1 * a[3]);
    *(__half2*)&w1.z = __floats2half2_rn(s1 * a[4], s1 * a[5]);
    *(__half2*)&w1.w = __floats2half2_rn(s1 * a[6], s1 * a[7]);
    *(__half2*)&w2.x = __floats2half2_rn(s2 * a[0], s2 * a[1]);
    *(__half2*)&w2.y = __floats2half2_rn(s2 * a[2], s2 * a[3]);
    *(__half2*)&w2.z = __floats2half2_rn(s2 * a[4], s2 * a[5]);
    *(__half2*)&w2.w = __floats2half2_rn(s2 * a[6], s2 * a[7]);
    ((uint4*)X1h)[node * 8 + lane] = w1;
    ((uint4*)X1s)[node * 8 + lane] = w2;
}

// ---------------- SpMM2: X2h = half(-2*dinv.*(A X1s) - hh) --------------------
__global__ void k_spmm2(const __half* __restrict__ x1s, const __half* __restrict__ z,
                        __half* __restrict__ X2h) {
    int node = blockIdx.x * (blockDim.x >> 3) + (threadIdx.x >> 3);
    int lane = threadIdx.x & 7;
    if (node >= NN) return;
    int s = g_rowptr[node], e = g_rowptr[node + 1];
    float a[8] = {0.f, 0.f, 0.f, 0.f, 0.f, 0.f, 0.f, 0.f};
    gather_rows((const uint4*)x1s, s, e, lane, a);
    float m = -2.f * g_dinv[node];
    uint4 zv = ((const uint4*)z)[node * 8 + lane];
    float2 z0 = __half22float2(*(const __half2*)&zv.x);
    float2 z1 = __half22float2(*(const __half2*)&zv.y);
    float2 z2 = __half22float2(*(const __half2*)&zv.z);
    float2 z3 = __half22float2(*(const __half2*)&zv.w);
    uint4 w;
    *(__half2*)&w.x = __floats2half2_rn(m * a[0] - z0.x, m * a[1] - z0.y);
    *(__half2*)&w.y = __floats2half2_rn(m * a[2] - z1.x, m * a[3] - z1.y);
    *(__half2*)&w.z = __floats2half2_rn(m * a[4] - z2.x, m * a[5] - z2.y);
    *(__half2*)&w.w = __floats2half2_rn(m * a[6] - z3.x, m * a[7] - z3.y);
    ((uint4*)X2h)[node * 8 + lane] = w;
}

// ---------------- GEMM (HMMA): out = [X0|X1|X2] @ W + b -----------------------
__global__ void k_gemm(const __half* __restrict__ x0, const __half* __restrict__ x1,
                       const __half* __restrict__ x2,
                       const float* __restrict__ W, const float* __restrict__ bias,
                       __half* __restrict__ outH, __half* __restrict__ outS, int relu) {
    __shared__ __align__(16) __half Xs[128 * 72];
    __shared__ __align__(16) __half Ws[64 * 72];
    int tid = threadIdx.x;
    int warp = tid >> 5, lane = tid & 31;
    int n0 = blockIdx.x * 128;

    float acc[2][8][4];
    #pragma unroll
    for (int tm = 0; tm < 2; tm++)
        #pragma unroll
        for (int nt = 0; nt < 8; nt++)
            #pragma unroll
            for (int q = 0; q < 4; q++) acc[tm][nt][q] = 0.f;

    const __half* xp[3] = {x0, x1, x2};
    for (int p = 0; p < 3; p++) {
        const __half* xc = xp[p];
        #pragma unroll
        for (int i = 0; i < 8; i++) {
            int li = i * 128 + tid;
            int row = li >> 3, c = li & 7;
            int gn = n0 + row;
            uint4 v = (gn < NN) ? ((const uint4*)xc)[gn * 8 + c]
                                : make_uint4(0u, 0u, 0u, 0u);
            *(uint4*)&Xs[row * 72 + c * 8] = v;
        }
        #pragma unroll
        for (int i = 0; i < 8; i++) {
            int li = i * 128 + tid;
            int row = li >> 4, c = li & 15;
            float4 w = ((const float4*)(W + p * 4096))[li];
            __half2 h01 = __floats2half2_rn(w.x, w.y);
            __half2 h23 = __floats2half2_rn(w.z, w.w);
            uint2 pk;
            pk.x = *(uint32_t*)&h01;
            pk.y = *(uint32_t*)&h23;
            *(uint2*)&Ws[row * 72 + c * 4] = pk;
        }
        __syncthreads();
        #pragma unroll
        for (int ks = 0; ks < 4; ks++) {
            int kb = ks * 16;
            uint32_t A[2][4];
            #pragma unroll
            for (int tm = 0; tm < 2; tm++) {
                int r = warp * 32 + tm * 16 + (lane & 15);
                ldmx4(A[tm], smem_u32(&Xs[r * 72 + kb + (lane >> 4) * 8]));
            }
            uint32_t B[8][2];
            #pragma unroll
            for (int g = 0; g < 4; g++) {
                uint32_t t[4];
                int krow = kb + (lane & 15);
                ldmx4t(t, smem_u32(&Ws[krow * 72 + g * 16 + (lane >> 4) * 8]));
                B[g * 2 + 0][0] = t[0]; B[g * 2 + 0][1] = t[1];
                B[g * 2 + 1][0] = t[2]; B[g * 2 + 1][1] = t[3];
            }
            #pragma unroll
            for (int tm = 0; tm < 2; tm++)
                #pragma unroll
                for (int nt = 0; nt < 8; nt++)
                    mma16816(acc[tm][nt], A[tm], B[nt]);
        }
        __syncthreads();
    }

    int col = 2 * (lane & 3);
    #pragma unroll
    for (int tm = 0; tm < 2; tm++) {
        #pragma unroll
        for (int hh = 0; hh < 2; hh++) {
            int node = n0 + warp * 32 + tm * 16 + (lane >> 2) + hh * 8;
            if (node >= NN) continue;
            float di = g_dinv[node];
            #pragma unroll
            for (int nt = 0; nt < 8; nt++) {
                int f = nt * 8 + col;
                float2 bv = *(const float2*)&bias[f];
                float v0 = acc[tm][nt][hh * 2 + 0] + bv.x;
                float v1 = acc[tm][nt][hh * 2 + 1] + bv.y;
                if (relu) { v0 = fmaxf(v0, 0.f); v1 = fmaxf(v1, 0.f); }
                *(__half2*)&outH[node * DH + f] = __floats2half2_rn(v0, v1);
                if (outS)
                    *(__half2*)&outS[node * DH + f] = __floats2half2_rn(v0 * di, v1 * di);
            }
        }
    }
}

// ---------------- readout ----------------
__global__ void k_pool(const __half* __restrict__ h, const int* __restrict__ gids) {
    int g = blockIdx.x;
    __shared__ int bnd[2];
    if (threadIdx.x < 2) {
        int target = g + threadIdx.x;
        int lo = 0, hi = NN;
        while (lo < hi) {
            int mid = (lo + hi) >> 1;
            if (gids[mid] < target) lo = mid + 1; else hi = mid;
        }
        bnd[threadIdx.x] = lo;
    }
    __syncthreads();
    int s = bnd[0], e = bnd[1];
    int f4 = threadIdx.x & 7;
    int way = threadIdx.x >> 3;
    float a[8] = {0.f, 0.f, 0.f, 0.f, 0.f, 0.f, 0.f, 0.f};
    for (int n = s + way; n < e; n += 32) {
        uint4 v = ((const uint4*)(h + n * DH))[f4];
        acc8(a, v);
    }
    __shared__ float sm[32][64];
    #pragma unroll
    for (int j = 0; j < 8; j++) sm[way][f4 * 8 + j] = a[j];
    __syncthreads();
    if (threadIdx.x < 64) {
        float v = 0.f;
        #pragma unroll 8
        for (int w = 0; w < 32; w++) v += sm[w][threadIdx.x];
        float cnt = (float)(e - s);
        g_hg[g * DH + threadIdx.x] = v / fmaxf(cnt, 1.f);
    }
}

__global__ void k_mlp(const float* __restrict__ M0w, const float* __restrict__ M0b,
                      const float* __restrict__ M1w, const float* __restrict__ M1b,
                      const float* __restrict__ M2w, const float* __restrict__ M2b,
                      float* __restrict__ out) {
    __shared__ float h0[NG * 64];
    __shared__ float h1[NG * 32];
    __shared__ float h2[NG * 16];
    int tid = threadIdx.x;
    for (int i = tid; i < NG * 64; i += blockDim.x) h0[i] = g_hg[i];
    __syncthreads();
    if (tid < NG * 32) {
        int g = tid >> 5, f = tid & 31;
        float a = M0b[f];
        #pragma unroll
        for (int k = 0; k < 64; k++) a += h0[g * 64 + k] * M0w[k * 32 + f];
        h1[tid] = fmaxf(a, 0.f);
    }
    __syncthreads();
    if (tid < NG * 16) {
        int g = tid >> 4, f = tid & 15;
        float a = M1b[f];
        #pragma unroll
        for (int k = 0; k < 32; k++) a += h1[g * 32 + k] * M1w[k * 16 + f];
        h2[tid] = fmaxf(a, 0.f);
    }
    __syncthreads();
    if (tid < NG * 3) {
        int g = tid / 3, f = tid % 3;
        float a = M2b[f];
        #pragma unroll
        for (int k = 0; k < 16; k++) a += h2[g * 16 + k] * M2w[k * 3 + f];
        out[tid] = a;
    }
}

// ---------------- launch ----------------
extern "C" void kernel_launch(void* const* d_in, const int* in_sizes, int n_in,
                              void* d_out, int out_size) {
    const float* h    = (const float*)d_in[0];
    const int*   src  = (const int*)d_in[1];
    const int*   dst  = (const int*)d_in[2];
    const int*   gids = (const int*)d_in[3];
    const float* W0   = (const float*)d_in[4];
    const float* b0   = (const float*)d_in[5];
    const float* W1   = (const float*)d_in[6];
    const float* b1   = (const float*)d_in[7];
    const float* W2   = (const float*)d_in[8];
    const float* b2   = (const float*)d_in[9];
    const float* M0w  = (const float*)d_in[10];
    const float* M0b  = (const float*)d_in[11];
    const float* M1w  = (const float*)d_in[12];
    const float* M1b  = (const float*)d_in[13];
    const float* M2w  = (const float*)d_in[14];
    const float* M2b  = (const float*)d_in[15];
    float* out = (float*)d_out;

    __half *pHh, *pHs, *pX1h, *pX1s, *pX2h;
    int *pDeg;
    ull *pState;
    cudaGetSymbolAddress((void**)&pHh, g_hh);
    cudaGetSymbolAddress((void**)&pHs, g_hs);
    cudaGetSymbolAddress((void**)&pX1h, g_x1h);
    cudaGetSymbolAddress((void**)&pX1s, g_x1s);
    cudaGetSymbolAddress((void**)&pX2h, g_x2h);
    cudaGetSymbolAddress((void**)&pDeg, g_deg);
    cudaGetSymbolAddress((void**)&pState, g_state);

    const int nb_e8 = (NE / 8 + 255) / 256;
    const int nb_spmm = (NN + 31) / 32;
    const int nb_gemm = (NN + 127) / 128;
    const int nb_pre = (NN * 32 + 255) / 256;

    // CSR build
    cudaMemsetAsync(pDeg, 0, NN * sizeof(int));
    cudaMemsetAsync(pState, 0, SCAN_NB * sizeof(ull));
    k_hist<<<nb_e8, 256>>>(dst);
    k_scan<<<SCAN_NB, 1024>>>();
    k_fill<<<nb_e8, 256>>>(src, dst);

    // layer 0
    k_pre<<<nb_pre, 256>>>(h);
    k_spmm1<<<nb_spmm, 256>>>(pHs, pX1h, pX1s);
    k_spmm2<<<nb_spmm, 256>>>(pX1s, pHh, pX2h);
    k_gemm<<<nb_gemm, 128>>>(pHh, pX1h, pX2h, W0, b0, pHh, pHs, 1);

    // layer 1
    k_spmm1<<<nb_spmm, 256>>>(pHs, pX1h, pX1s);
    k_spmm2<<<nb_spmm, 256>>>(pX1s, pHh, pX2h);
    k_gemm<<<nb_gemm, 128>>>(pHh, pX1h, pX2h, W1, b1, pHh, pHs, 1);

    // layer 2 (no relu, fp16 out only)
    k_spmm1<<<nb_spmm, 256>>>(pHs, pX1h, pX1s);
    k_spmm2<<<nb_spmm, 256>>>(pX1s, pHh, pX2h);
    k_gemm<<<nb_gemm, 128>>>(pHh, pX1h, pX2h, W2, b2, pHh, nullptr, 0);

    // readout
    k_pool<<<NG, 256>>>(pHh, gids);
    k_mlp<<<1, 1024>>>(M0w, M0b, M1w, M1b, M2w, M2b, out);
}

// round 17
// speedup vs baseline: 1.1294x; 1.0458x over previous
#include <cuda_runtime.h>
#include <cuda_fp16.h>
#include <math.h>
#include <stdint.h>

#define NN 100000
#define NE 1600000
#define NG 32
#define DH 64
#define SCAN_NB 98
#define NB_FILL 782            // ceil(NE/8 / 256)
#define NB_PRE  6250           // NN*16 float4-quads / 256

typedef unsigned long long ull;

// ---------------- scratch ----------------
__device__ int      g_deg[NN];
__device__ float    g_dinv[NN];
__device__ int      g_rowptr[NN + 1];
__device__ int      g_col[NE];
__device__ uint16_t g_rank[NE];
__device__ ull      g_state[SCAN_NB];
__device__ __half   g_hh[NN * DH];
__device__ __half   g_hs[NN * DH];
__device__ __half   g_x1h[NN * DH];
__device__ __half   g_x1s[NN * DH];
__device__ __half   g_x2h[NN * DH];
__device__ float    g_hg[NG * DH];

// ---------------- mma helpers ----------------
__device__ __forceinline__ uint32_t smem_u32(const void* p) {
    return (uint32_t)__cvta_generic_to_shared(p);
}
__device__ __forceinline__ void ldmx4(uint32_t* r, uint32_t addr) {
    asm volatile("ldmatrix.sync.aligned.m8n8.x4.shared.b16 {%0,%1,%2,%3}, [%4];"
                 : "=r"(r[0]), "=r"(r[1]), "=r"(r[2]), "=r"(r[3]) : "r"(addr));
}
__device__ __forceinline__ void ldmx4t(uint32_t* r, uint32_t addr) {
    asm volatile("ldmatrix.sync.aligned.m8n8.x4.trans.shared.b16 {%0,%1,%2,%3}, [%4];"
                 : "=r"(r[0]), "=r"(r[1]), "=r"(r[2]), "=r"(r[3]) : "r"(addr));
}
__device__ __forceinline__ void mma16816(float* c, const uint32_t* a, const uint32_t* b) {
    asm volatile("mma.sync.aligned.m16n8k16.row.col.f32.f16.f16.f32 "
                 "{%0,%1,%2,%3}, {%4,%5,%6,%7}, {%8,%9}, {%0,%1,%2,%3};"
                 : "+f"(c[0]), "+f"(c[1]), "+f"(c[2]), "+f"(c[3])
                 : "r"(a[0]), "r"(a[1]), "r"(a[2]), "r"(a[3]), "r"(b[0]), "r"(b[1]));
}

// ---------------- CSR build ----------------
// 8 edges/thread; store per-edge rank for atomic-free fill
__global__ void k_hist(const int* __restrict__ dst) {
    int t = blockIdx.x * blockDim.x + threadIdx.x;
    if (t * 8 >= NE) return;
    int4 d0 = ((const int4*)dst)[t * 2];
    int4 d1 = ((const int4*)dst)[t * 2 + 1];
    int r0 = atomicAdd(&g_deg[d0.x], 1);
    int r1 = atomicAdd(&g_deg[d0.y], 1);
    int r2 = atomicAdd(&g_deg[d0.z], 1);
    int r3 = atomicAdd(&g_deg[d0.w], 1);
    int r4 = atomicAdd(&g_deg[d1.x], 1);
    int r5 = atomicAdd(&g_deg[d1.y], 1);
    int r6 = atomicAdd(&g_deg[d1.z], 1);
    int r7 = atomicAdd(&g_deg[d1.w], 1);
    ushort4 a, b;
    a.x = (uint16_t)r0; a.y = (uint16_t)r1; a.z = (uint16_t)r2; a.w = (uint16_t)r3;
    b.x = (uint16_t)r4; b.y = (uint16_t)r5; b.z = (uint16_t)r6; b.w = (uint16_t)r7;
    ((ushort4*)g_rank)[t * 2] = a;
    ((ushort4*)g_rank)[t * 2 + 1] = b;
}

// single-pass scan over 98 blocks (all resident -> spin safe): rowptr + dinv
__global__ void k_scan() {
    int tid = threadIdx.x, bid = blockIdx.x;
    int i = bid * 1024 + tid;
    int deg = (i < NN) ? g_deg[i] : 0;
    int lane = tid & 31, wid = tid >> 5;

    int incl = deg;
    #pragma unroll
    for (int o = 1; o < 32; o <<= 1) {
        int t = __shfl_up_sync(0xFFFFFFFFu, incl, o);
        if (lane >= o) incl += t;
    }
    __shared__ int wsum[32];
    if (lane == 31) wsum[wid] = incl;
    __syncthreads();
    if (wid == 0) {
        int v = wsum[lane];
        int s = v;
        #pragma unroll
        for (int o = 1; o < 32; o <<= 1) {
            int t = __shfl_up_sync(0xFFFFFFFFu, s, o);
            if (lane >= o) s += t;
        }
        wsum[lane] = s - v;
    }
    __syncthreads();
    int excl = incl - deg + wsum[wid];

    __shared__ int btotal;
    if (tid == 1023) btotal = excl + deg;
    __syncthreads();
    if (tid == 0) {
        __threadfence();
        atomicExch(&g_state[bid], ((ull)btotal) | (1ull << 40));
    }
    __shared__ int aggs[SCAN_NB];
    if (tid < SCAN_NB) {
        ull v;
        do { v = atomicAdd(&g_state[tid], 0ull); } while (!(v >> 40));
        aggs[tid] = (int)(v & 0xFFFFFFFFull);
    }
    __syncthreads();
    __shared__ int sbase, stotal;
    if (tid == 0) {
        int b = 0, tot = 0;
        #pragma unroll 2
        for (int j = 0; j < SCAN_NB; j++) {
            if (j < bid) b += aggs[j];
            tot += aggs[j];
        }
        sbase = b; stotal = tot;
    }
    __syncthreads();
    if (i < NN) {
        g_rowptr[i] = sbase + excl;
        g_dinv[i] = rsqrtf(fmaxf((float)deg, 1.0f));
    }
    if (bid == SCAN_NB - 1 && tid == 0) g_rowptr[NN] = stotal;
}

// ---------------- fused fill + layer-0 prescale -------------------------------
// Blocks [0, NB_FILL): atomic-free CSR fill (pos = rowptr[dst] + rank[e]).
// Blocks [NB_FILL, NB_FILL+NB_PRE): hs = half(dinv.*x), hh = half(x), float4/thr.
// Both depend only on k_scan; heterogeneous blocks overlap DRAM-read (pre)
// with L2-scatter (fill) across SMs in one launch.
__global__ void k_fillpre(const int* __restrict__ src, const int* __restrict__ dst,
                          const float* __restrict__ x) {
    int bid = blockIdx.x;
    if (bid < NB_FILL) {
        int t = bid * blockDim.x + threadIdx.x;
        if (t * 8 >= NE) return;
        int4 d0 = ((const int4*)dst)[t * 2];
        int4 d1 = ((const int4*)dst)[t * 2 + 1];
        int4 s0 = ((const int4*)src)[t * 2];
        int4 s1 = ((const int4*)src)[t * 2 + 1];
        ushort4 a = ((const ushort4*)g_rank)[t * 2];
        ushort4 b = ((const ushort4*)g_rank)[t * 2 + 1];
        g_col[g_rowptr[d0.x] + a.x] = s0.x;
        g_col[g_rowptr[d0.y] + a.y] = s0.y;
        g_col[g_rowptr[d0.z] + a.z] = s0.z;
        g_col[g_rowptr[d0.w] + a.w] = s0.w;
        g_col[g_rowptr[d1.x] + b.x] = s1.x;
        g_col[g_rowptr[d1.y] + b.y] = s1.y;
        g_col[g_rowptr[d1.z] + b.z] = s1.z;
        g_col[g_rowptr[d1.w] + b.w] = s1.w;
    } else {
        int i = (bid - NB_FILL) * blockDim.x + threadIdx.x;   // float4 index
        if (i < NN * 16) {
            float4 v = ((const float4*)x)[i];
            float di = g_dinv[i >> 4];
            __half2 s0 = __floats2half2_rn(v.x * di, v.y * di);
            __half2 s1 = __floats2half2_rn(v.z * di, v.w * di);
            __half2 h0 = __floats2half2_rn(v.x, v.y);
            __half2 h1 = __floats2half2_rn(v.z, v.w);
            uint2 ps, ph;
            ps.x = *(uint32_t*)&s0; ps.y = *(uint32_t*)&s1;
            ph.x = *(uint32_t*)&h0; ph.y = *(uint32_t*)&h1;
            ((uint2*)g_hs)[i] = ps;
            ((uint2*)g_hh)[i] = ph;
        }
    }
}

// ---------------- gather helpers (measured-best x4 form) ----------------------
__device__ __forceinline__ void acc8(float* a, uint4 v) {
    float2 f0 = __half22float2(*(const __half2*)&v.x);
    float2 f1 = __half22float2(*(const __half2*)&v.y);
    float2 f2 = __half22float2(*(const __half2*)&v.z);
    float2 f3 = __half22float2(*(const __half2*)&v.w);
    a[0] += f0.x; a[1] += f0.y; a[2] += f1.x; a[3] += f1.y;
    a[4] += f2.x; a[5] += f2.y; a[6] += f3.x; a[7] += f3.y;
}

__device__ __forceinline__ void gather_rows(const uint4* __restrict__ yp,
                                            int s, int e, int lane, float* a) {
    int i = s;
    for (; i + 4 <= e; i += 4) {
        int c0 = g_col[i], c1 = g_col[i + 1], c2 = g_col[i + 2], c3 = g_col[i + 3];
        uint4 v0 = yp[c0 * 8 + lane];
        uint4 v1 = yp[c1 * 8 + lane];
        uint4 v2 = yp[c2 * 8 + lane];
        uint4 v3 = yp[c3 * 8 + lane];
        acc8(a, v0); acc8(a, v1); acc8(a, v2); acc8(a, v3);
    }
    for (; i < e; i++) {
        uint4 v = yp[g_col[i] * 8 + lane];
        acc8(a, v);
    }
}

// ---------------- SpMM1: X1h = half(-dinv.*(A hs)); X1s = half(dinv.*X1) ------
__global__ void k_spmm1(const __half* __restrict__ ys, __half* __restrict__ X1h,
                        __half* __restrict__ X1s) {
    int node = blockIdx.x * (blockDim.x >> 3) + (threadIdx.x >> 3);
    int lane = threadIdx.x & 7;
    if (node >= NN) return;
    int s = g_rowptr[node], e = g_rowptr[node + 1];
    float a[8] = {0.f, 0.f, 0.f, 0.f, 0.f, 0.f, 0.f, 0.f};
    gather_rows((const uint4*)ys, s, e, lane, a);
    float di = g_dinv[node];
    float s1 = -di;
    float s2 = -di * di;
    uint4 w1, w2;
    *(__half2*)&w1.x = __floats2half2_rn(s1 * a[0], s1 * a[1]);
    *(__half2*)&w1.y = __floats2half2_rn(s1 * a[2], s1 * a[3]);
    *(__half2*)&w1.z = __floats2half2_rn(s1 * a[4], s1 * a[5]);
    *(__half2*)&w1.w = __floats2half2_rn(s1 * a[6], s1 * a[7]);
    *(__half2*)&w2.x = __floats2half2_rn(s2 * a[0], s2 * a[1]);
    *(__half2*)&w2.y = __floats2half2_rn(s2 * a[2], s2 * a[3]);
    *(__half2*)&w2.z = __floats2half2_rn(s2 * a[4], s2 * a[5]);
    *(__half2*)&w2.w = __floats2half2_rn(s2 * a[6], s2 * a[7]);
    ((uint4*)X1h)[node * 8 + lane] = w1;
    ((uint4*)X1s)[node * 8 + lane] = w2;
}

// ---------------- SpMM2: X2h = half(-2*dinv.*(A X1s) - hh) --------------------
__global__ void k_spmm2(const __half* __restrict__ x1s, const __half* __restrict__ z,
                        __half* __restrict__ X2h) {
    int node = blockIdx.x * (blockDim.x >> 3) + (threadIdx.x >> 3);
    int lane = threadIdx.x & 7;
    if (node >= NN) return;
    int s = g_rowptr[node], e = g_rowptr[node + 1];
    float a[8] = {0.f, 0.f, 0.f, 0.f, 0.f, 0.f, 0.f, 0.f};
    gather_rows((const uint4*)x1s, s, e, lane, a);
    float m = -2.f * g_dinv[node];
    uint4 zv = ((const uint4*)z)[node * 8 + lane];
    float2 z0 = __half22float2(*(const __half2*)&zv.x);
    float2 z1 = __half22float2(*(const __half2*)&zv.y);
    float2 z2 = __half22float2(*(const __half2*)&zv.z);
    float2 z3 = __half22float2(*(const __half2*)&zv.w);
    uint4 w;
    *(__half2*)&w.x = __floats2half2_rn(m * a[0] - z0.x, m * a[1] - z0.y);
    *(__half2*)&w.y = __floats2half2_rn(m * a[2] - z1.x, m * a[3] - z1.y);
    *(__half2*)&w.z = __floats2half2_rn(m * a[4] - z2.x, m * a[5] - z2.y);
    *(__half2*)&w.w = __floats2half2_rn(m * a[6] - z3.x, m * a[7] - z3.y);
    ((uint4*)X2h)[node * 8 + lane] = w;
}

// ---------------- GEMM (HMMA): out = [X0|X1|X2] @ W + b -----------------------
__global__ void k_gemm(const __half* __restrict__ x0, const __half* __restrict__ x1,
                       const __half* __restrict__ x2,
                       const float* __restrict__ W, const float* __restrict__ bias,
                       __half* __restrict__ outH, __half* __restrict__ outS, int relu) {
    __shared__ __align__(16) __half Xs[128 * 72];
    __shared__ __align__(16) __half Ws[64 * 72];
    int tid = threadIdx.x;
    int warp = tid >> 5, lane = tid & 31;
    int n0 = blockIdx.x * 128;

    float acc[2][8][4];
    #pragma unroll
    for (int tm = 0; tm < 2; tm++)
        #pragma unroll
        for (int nt = 0; nt < 8; nt++)
            #pragma unroll
            for (int q = 0; q < 4; q++) acc[tm][nt][q] = 0.f;

    const __half* xp[3] = {x0, x1, x2};
    for (int p = 0; p < 3; p++) {
        const __half* xc = xp[p];
        #pragma unroll
        for (int i = 0; i < 8; i++) {
            int li = i * 128 + tid;
            int row = li >> 3, c = li & 7;
            int gn = n0 + row;
            uint4 v = (gn < NN) ? ((const uint4*)xc)[gn * 8 + c]
                                : make_uint4(0u, 0u, 0u, 0u);
            *(uint4*)&Xs[row * 72 + c * 8] = v;
        }
        #pragma unroll
        for (int i = 0; i < 8; i++) {
            int li = i * 128 + tid;
            int row = li >> 4, c = li & 15;
            float4 w = ((const float4*)(W + p * 4096))[li];
            __half2 h01 = __floats2half2_rn(w.x, w.y);
            __half2 h23 = __floats2half2_rn(w.z, w.w);
            uint2 pk;
            pk.x = *(uint32_t*)&h01;
            pk.y = *(uint32_t*)&h23;
            *(uint2*)&Ws[row * 72 + c * 4] = pk;
        }
        __syncthreads();
        #pragma unroll
        for (int ks = 0; ks < 4; ks++) {
            int kb = ks * 16;
            uint32_t A[2][4];
            #pragma unroll
            for (int tm = 0; tm < 2; tm++) {
                int r = warp * 32 + tm * 16 + (lane & 15);
                ldmx4(A[tm], smem_u32(&Xs[r * 72 + kb + (lane >> 4) * 8]));
            }
            uint32_t B[8][2];
            #pragma unroll
            for (int g = 0; g < 4; g++) {
                uint32_t t[4];
                int krow = kb + (lane & 15);
                ldmx4t(t, smem_u32(&Ws[krow * 72 + g * 16 + (lane >> 4) * 8]));
                B[g * 2 + 0][0] = t[0]; B[g * 2 + 0][1] = t[1];
                B[g * 2 + 1][0] = t[2]; B[g * 2 + 1][1] = t[3];
            }
            #pragma unroll
            for (int tm = 0; tm < 2; tm++)
                #pragma unroll
                for (int nt = 0; nt < 8; nt++)
                    mma16816(acc[tm][nt], A[tm], B[nt]);
        }
        __syncthreads();
    }

    int col = 2 * (lane & 3);
    #pragma unroll
    for (int tm = 0; tm < 2; tm++) {
        #pragma unroll
        for (int hh = 0; hh < 2; hh++) {
            int node = n0 + warp * 32 + tm * 16 + (lane >> 2) + hh * 8;
            if (node >= NN) continue;
            float di = g_dinv[node];
            #pragma unroll
            for (int nt = 0; nt < 8; nt++) {
                int f = nt * 8 + col;
                float2 bv = *(const float2*)&bias[f];
                float v0 = acc[tm][nt][hh * 2 + 0] + bv.x;
                float v1 = acc[tm][nt][hh * 2 + 1] + bv.y;
                if (relu) { v0 = fmaxf(v0, 0.f); v1 = fmaxf(v1, 0.f); }
                *(__half2*)&outH[node * DH + f] = __floats2half2_rn(v0, v1);
                if (outS)
                    *(__half2*)&outS[node * DH + f] = __floats2half2_rn(v0 * di, v1 * di);
            }
        }
    }
}

// ---------------- readout ----------------
__global__ void k_pool(const __half* __restrict__ h, const int* __restrict__ gids) {
    int g = blockIdx.x;
    __shared__ int bnd[2];
    if (threadIdx.x < 2) {
        int target = g + threadIdx.x;
        int lo = 0, hi = NN;
        while (lo < hi) {
            int mid = (lo + hi) >> 1;
            if (gids[mid] < target) lo = mid + 1; else hi = mid;
        }
        bnd[threadIdx.x] = lo;
    }
    __syncthreads();
    int s = bnd[0], e = bnd[1];
    int f4 = threadIdx.x & 7;
    int way = threadIdx.x >> 3;
    float a[8] = {0.f, 0.f, 0.f, 0.f, 0.f, 0.f, 0.f, 0.f};
    for (int n = s + way; n < e; n += 32) {
        uint4 v = ((const uint4*)(h + n * DH))[f4];
        acc8(a, v);
    }
    __shared__ float sm[32][64];
    #pragma unroll
    for (int j = 0; j < 8; j++) sm[way][f4 * 8 + j] = a[j];
    __syncthreads();
    if (threadIdx.x < 64) {
        float v = 0.f;
        #pragma unroll 8
        for (int w = 0; w < 32; w++) v += sm[w][threadIdx.x];
        float cnt = (float)(e - s);
        g_hg[g * DH + threadIdx.x] = v / fmaxf(cnt, 1.f);
    }
}

__global__ void k_mlp(const float* __restrict__ M0w, const float* __restrict__ M0b,
                      const float* __restrict__ M1w, const float* __restrict__ M1b,
                      const float* __restrict__ M2w, const float* __restrict__ M2b,
                      float* __restrict__ out) {
    __shared__ float h0[NG * 64];
    __shared__ float h1[NG * 32];
    __shared__ float h2[NG * 16];
    int tid = threadIdx.x;
    for (int i = tid; i < NG * 64; i += blockDim.x) h0[i] = g_hg[i];
    __syncthreads();
    if (tid < NG * 32) {
        int g = tid >> 5, f = tid & 31;
        float a = M0b[f];
        #pragma unroll
        for (int k = 0; k < 64; k++) a += h0[g * 64 + k] * M0w[k * 32 + f];
        h1[tid] = fmaxf(a, 0.f);
    }
    __syncthreads();
    if (tid < NG * 16) {
        int g = tid >> 4, f = tid & 15;
        float a = M1b[f];
        #pragma unroll
        for (int k = 0; k < 32; k++) a += h1[g * 32 + k] * M1w[k * 16 + f];
        h2[tid] = fmaxf(a, 0.f);
    }
    __syncthreads();
    if (tid < NG * 3) {
        int g = tid / 3, f = tid % 3;
        float a = M2b[f];
        #pragma unroll
        for (int k = 0; k < 16; k++) a += h2[g * 16 + k] * M2w[k * 3 + f];
        out[tid] = a;
    }
}

// ---------------- launch ----------------
extern "C" void kernel_launch(void* const* d_in, const int* in_sizes, int n_in,
                              void* d_out, int out_size) {
    const float* h    = (const float*)d_in[0];
    const int*   src  = (const int*)d_in[1];
    const int*   dst  = (const int*)d_in[2];
    const int*   gids = (const int*)d_in[3];
    const float* W0   = (const float*)d_in[4];
    const float* b0   = (const float*)d_in[5];
    const float* W1   = (const float*)d_in[6];
    const float* b1   = (const float*)d_in[7];
    const float* W2   = (const float*)d_in[8];
    const float* b2   = (const float*)d_in[9];
    const float* M0w  = (const float*)d_in[10];
    const float* M0b  = (const float*)d_in[11];
    const float* M1w  = (const float*)d_in[12];
    const float* M1b  = (const float*)d_in[13];
    const float* M2w  = (const float*)d_in[14];
    const float* M2b  = (const float*)d_in[15];
    float* out = (float*)d_out;

    __half *pHh, *pHs, *pX1h, *pX1s, *pX2h;
    int *pDeg;
    ull *pState;
    cudaGetSymbolAddress((void**)&pHh, g_hh);
    cudaGetSymbolAddress((void**)&pHs, g_hs);
    cudaGetSymbolAddress((void**)&pX1h, g_x1h);
    cudaGetSymbolAddress((void**)&pX1s, g_x1s);
    cudaGetSymbolAddress((void**)&pX2h, g_x2h);
    cudaGetSymbolAddress((void**)&pDeg, g_deg);
    cudaGetSymbolAddress((void**)&pState, g_state);

    const int nb_e8 = (NE / 8 + 255) / 256;
    const int nb_spmm = (NN + 31) / 32;
    const int nb_gemm = (NN + 127) / 128;

    // CSR build + layer-0 prescale (fill and pre fused for overlap)
    cudaMemsetAsync(pDeg, 0, NN * sizeof(int));
    cudaMemsetAsync(pState, 0, SCAN_NB * sizeof(ull));
    k_hist<<<nb_e8, 256>>>(dst);
    k_scan<<<SCAN_NB, 1024>>>();
    k_fillpre<<<NB_FILL + NB_PRE, 256>>>(src, dst, h);

    // layer 0
    k_spmm1<<<nb_spmm, 256>>>(pHs, pX1h, pX1s);
    k_spmm2<<<nb_spmm, 256>>>(pX1s, pHh, pX2h);
    k_gemm<<<nb_gemm, 128>>>(pHh, pX1h, pX2h, W0, b0, pHh, pHs, 1);

    // layer 1
    k_spmm1<<<nb_spmm, 256>>>(pHs, pX1h, pX1s);
    k_spmm2<<<nb_spmm, 256>>>(pX1s, pHh, pX2h);
    k_gemm<<<nb_gemm, 128>>>(pHh, pX1h, pX2h, W1, b1, pHh, pHs, 1);

    // layer 2 (no relu, fp16 out only)
    k_spmm1<<<nb_spmm, 256>>>(pHs, pX1h, pX1s);
    k_spmm2<<<nb_spmm, 256>>>(pX1s, pHh, pX2h);
    k_gemm<<<nb_gemm, 128>>>(pHh, pX1h, pX2h, W2, b2, pHh, nullptr, 0);

    // readout
    k_pool<<<NG, 256>>>(pHh, gids);
    k_mlp<<<1, 1024>>>(M0w, M0b, M1w, M1b, M2w, M2b, out);
}